// round 14
// baseline (speedup 1.0000x reference)
#include <cuda_runtime.h>
#include <cuda_fp16.h>

#define BN   4
#define NF   8
#define CC   8
#define NPIX (512 * 512)
#define NG   (NPIX / 4)              // 65536 pixel-groups per image
#define BPI  37                      // blocks per image
#define NBLK (BN * BPI)              // 148 = one block per SM
#define NGB  ((NG + BPI - 1) / BPI)  // 1772 groups per block (last: 1744)
#define NTHR 768
#define NW   (NTHR / 32)             // 24 warps
#define HALF (NTHR / 2)              // 384 threads per feature-half
#define WPH  (NW / 2)                // 12 warps per half

#define SPRED_HALF_B (NGB * 4 * 8)               // uint2 per pixel: 56704
#define SMEM_TOTAL   (2 * SPRED_HALF_B)          // 113408 (no label cache)

typedef unsigned long long ULL;

struct Scratch {
    float sums[BN][CC][NF];
    float counts[BN][CC];
    float dist[BN];
    unsigned int arrive;
    unsigned int release;
    unsigned int ticket;
};
__device__ Scratch g_s;   // zero-init at load; self-reset at end of every run

__device__ __forceinline__ ULL fadd2(ULL a, ULL b) {
    ULL d;
    asm("add.rn.f32x2 %0, %1, %2;" : "=l"(d) : "l"(a), "l"(b));
    return d;
}
__device__ __forceinline__ ULL pack2(float lo, float hi) {
    ULL r;
    asm("mov.b64 %0, {%1, %2};" : "=l"(r) : "f"(lo), "f"(hi));
    return r;
}
__device__ __forceinline__ void unpack2(ULL v, float& lo, float& hi) {
    asm("mov.b64 {%0, %1}, %2;" : "=f"(lo), "=f"(hi) : "l"(v));
}
// if (lab == c): a0 += p0; a1 += p1; cnt += inc  (setp + 3 predicated adds)
__device__ __forceinline__ void acc_if_eq(ULL& a0, ULL& a1, int& cnt,
                                          int lab, int c, int inc,
                                          ULL p0, ULL p1) {
    asm("{ .reg .pred p; setp.eq.s32 p, %3, %4;\n\t"
        "@p add.rn.f32x2 %0, %0, %6;\n\t"
        "@p add.rn.f32x2 %1, %1, %7;\n\t"
        "@p add.s32 %2, %2, %5; }"
        : "+l"(a0), "+l"(a1), "+r"(cnt)
        : "r"(lab), "r"(c), "r"(inc), "l"(p0), "l"(p1));
}
__device__ __forceinline__ float f4get(const float4 v, int i) {
    return i == 0 ? v.x : i == 1 ? v.y : i == 2 ? v.z : v.w;
}
__device__ __forceinline__ int i4get(const int4 v, int i) {
    return i == 0 ? v.x : i == 1 ? v.y : i == 2 ? v.z : v.w;
}
__device__ __forceinline__ unsigned h2u(float a, float b) {
    __half2 h = __floats2half2_rn(a, b);
    return *reinterpret_cast<unsigned*>(&h);
}
__device__ __forceinline__ float2 u2f2(unsigned u) {
    return __half22float2(*reinterpret_cast<__half2*>(&u));
}

__global__ void __launch_bounds__(NTHR, 1)
k_all(const float* __restrict__ pred, const int* __restrict__ tgt,
      float* __restrict__ out) {
    extern __shared__ unsigned char smem_raw[];
    uint2* spredA = (uint2*)smem_raw;                    // feats 0-3
    uint2* spredB = (uint2*)(smem_raw + SPRED_HALF_B);   // feats 4-7

    const int tid = threadIdx.x;
    const int bx  = blockIdx.x;
    const int img = bx / BPI;
    const int li  = bx % BPI;
    const int g0  = li * NGB;
    const int g1  = (g0 + NGB < NG) ? g0 + NGB : NG;
    const int range = g1 - g0;

    const int wid = tid >> 5, lane = tid & 31;
    const int halfid = (tid >= HALF) ? 1 : 0;   // 0: feats 0-3, 1: feats 4-7
    const int hw     = wid - halfid * WPH;      // warp id within half (0..11)

    const float4* p = (const float4*)(pred + (size_t)img * NF * NPIX) +
                      (size_t)(halfid * 4) * NG;
    const int4*   g = (const int4*)(tgt + (size_t)img * NPIX);
    uint2* sp = halfid ? spredB : spredA;

    // ====== Phase A: warp-chunked contiguous sweep; each half covers all
    // pixels for its 4 features ==============================================
    ULL acc[CC][2];
    int cnta = 0, cntb = 0;   // byte-packed pixel counts (half A only is used)
#pragma unroll
    for (int c = 0; c < CC; c++) { acc[c][0] = 0ull; acc[c][1] = 0ull; }

    {
        const int CH = (range + WPH - 1) / WPH;     // groups per warp-chunk
        const int cs = hw * CH;
        const int ce = (cs + CH < range) ? cs + CH : range;
        for (int base = cs; base < ce; base += 32) {
            int gl = base + lane;
            bool act = (gl < ce);
            int n = g0 + (act ? gl : cs);

            int4 lab4 = g[n];
            float4 v0 = p[0 * NG + n];
            float4 v1 = p[1 * NG + n];
            float4 v2 = p[2 * NG + n];
            float4 v3 = p[3 * NG + n];

#pragma unroll
            for (int px = 0; px < 4; px++) {
                float a0 = f4get(v0, px), a1 = f4get(v1, px);
                float a2 = f4get(v2, px), a3 = f4get(v3, px);
                if (act) {
                    uint2 hq;
                    hq.x = h2u(a0, a1);
                    hq.y = h2u(a2, a3);
                    sp[gl * 4 + px] = hq;
                }
                int lab = act ? i4get(lab4, px) : 255;
                ULL pr0 = pack2(a0, a1);
                ULL pr1 = pack2(a2, a3);
#pragma unroll
                for (int c = 0; c < 4; c++)
                    acc_if_eq(acc[c][0], acc[c][1], cnta, lab, c, 1 << (8 * c),
                              pr0, pr1);
#pragma unroll
                for (int c = 4; c < 8; c++)
                    acc_if_eq(acc[c][0], acc[c][1], cntb, lab, c,
                              1 << (8 * (c - 4)), pr0, pr1);
            }
        }
    }

    // full 32-lane warp tree-reduce (all lanes of a warp share one half)
    int icnt[CC];
#pragma unroll
    for (int c = 0; c < 4; c++) {
        icnt[c]     = (cnta >> (8 * c)) & 0xFF;
        icnt[c + 4] = (cntb >> (8 * c)) & 0xFF;
    }
#pragma unroll
    for (int c = 0; c < CC; c++) {
#pragma unroll
        for (int k = 0; k < 2; k++) {
            ULL x = acc[c][k];
#pragma unroll
            for (int o = 16; o > 0; o >>= 1)
                x = fadd2(x, __shfl_down_sync(0xffffffffu, x, o));
            acc[c][k] = x;
        }
        int ic = icnt[c];
#pragma unroll
        for (int o = 16; o > 0; o >>= 1) ic += __shfl_down_sync(0xffffffffu, ic, o);
        icnt[c] = ic;
    }

    __shared__ float sw[NW][CC][5];   // 4 half-features + count per cluster
    if (lane == 0) {
#pragma unroll
        for (int c = 0; c < CC; c++) {
#pragma unroll
            for (int k = 0; k < 2; k++) {
                float lo, hi;
                unpack2(acc[c][k], lo, hi);
                sw[wid][c][2 * k]     = lo;
                sw[wid][c][2 * k + 1] = hi;
            }
            sw[wid][c][4] = (float)icnt[c];
        }
    }
    __syncthreads();
    if (tid < 64) {
        int c = tid >> 3, f = tid & 7;
        float s = 0.f;
        if (f < 4) {
#pragma unroll
            for (int w = 0; w < WPH; w++) s += sw[w][c][f];
        } else {
#pragma unroll
            for (int w = WPH; w < NW; w++) s += sw[w][c][f - 4];
        }
        atomicAdd(&g_s.sums[img][c][f], s);
    } else if (tid < 72) {
        int c = tid - 64;
        float s = 0.f;
#pragma unroll
        for (int w = 0; w < WPH; w++) s += sw[w][c][4];  // counts: half A only
        atomicAdd(&g_s.counts[img][c], s);
    }
    __threadfence();
    __syncthreads();

    // ================= Grid barrier (148 resident blocks) ==================
    if (tid == 0) {
        unsigned int a = atomicAdd(&g_s.arrive, 1u);
        if (a == NBLK - 1) {
            atomicExch(&g_s.release, 1u);
        } else {
            volatile unsigned int* rel = &g_s.release;
            while (*rel == 0u) { __nanosleep(64); }
        }
    }
    __syncthreads();
    __threadfence();

    // ================= Phase B: hinge distance; pred from smem fp16,
    // labels re-read from global (L2-warm) ==================================
    __shared__ float4 smean0[CC];   // features 0-3 per label
    __shared__ float4 smean1[CC];   // features 4-7 per label
    if (tid < 64) {
        int c = tid >> 3, f = tid & 7;
        float m = __ldcg(&g_s.sums[img][c][f]) / __ldcg(&g_s.counts[img][c]);
        float* base = (f < 4) ? (float*)&smean0[c] : (float*)&smean1[c];
        base[f & 3] = m;
    }
    __syncthreads();

    float local = 0.f;
    {
        const int CH = (range + NW - 1) / NW;
        const int cs = wid * CH;
        const int ce = (cs + CH < range) ? cs + CH : range;
        for (int base = cs; base < ce; base += 32) {
            int gl = base + lane;
            bool act = (gl < ce);
            int gll = act ? gl : cs;
            int4 lab4 = __ldg(&g[g0 + gll]);
#pragma unroll
            for (int px = 0; px < 4; px++) {
                uint2 ha = spredA[gll * 4 + px];
                uint2 hb = spredB[gll * 4 + px];
                int lab = i4get(lab4, px);
                float4 m0 = smean0[lab];
                float4 m1 = smean1[lab];
                float2 q01 = u2f2(ha.x), q23 = u2f2(ha.y);
                float2 q45 = u2f2(hb.x), q67 = u2f2(hb.y);
                float d2 = 0.f, d;
                d = m0.x - q01.x; d2 = fmaf(d, d, d2);
                d = m0.y - q01.y; d2 = fmaf(d, d, d2);
                d = m0.z - q23.x; d2 = fmaf(d, d, d2);
                d = m0.w - q23.y; d2 = fmaf(d, d, d2);
                d = m1.x - q45.x; d2 = fmaf(d, d, d2);
                d = m1.y - q45.y; d2 = fmaf(d, d, d2);
                d = m1.z - q67.x; d2 = fmaf(d, d, d2);
                d = m1.w - q67.y; d2 = fmaf(d, d, d2);
                float t = sqrtf(d2) - 0.5f;           // DELTA_V
                t = fminf(fmaxf(t, 0.f), 100000.f);
                if (act) local = fmaf(t, t, local);
            }
        }
    }

#pragma unroll
    for (int o = 16; o > 0; o >>= 1)
        local += __shfl_down_sync(0xffffffffu, local, o);
    __shared__ float sred[NW];
    if (lane == 0) sred[wid] = local;
    __syncthreads();
    if (tid == 0) {
        float s = 0.f;
#pragma unroll
        for (int w = 0; w < NW; w++) s += sred[w];
        atomicAdd(&g_s.dist[img], s);
    }

    // ================= Last-block finalize =================================
    __shared__ bool s_last;
    __threadfence();
    if (tid == 0) {
        unsigned int t = atomicAdd(&g_s.ticket, 1u);
        s_last = (t == NBLK - 1);
    }
    __syncthreads();
    if (!s_last) return;

    __shared__ float smu[BN][CC][NF];
    __shared__ float s_ldist[BN], s_lreg[BN], s_inv[BN];
    float cnt_cache = 1.f;
    if (tid < 256) {
        int bb = tid >> 6, i = (tid >> 3) & 7, j = tid & 7;
        cnt_cache = __ldcg(&g_s.counts[bb][i]);
        smu[bb][i][j] = __ldcg(&g_s.sums[bb][i][j]) / cnt_cache;
    }
    if (tid < BN) { s_ldist[tid] = 0.f; s_lreg[tid] = 0.f; s_inv[tid] = 0.f; }
    __syncthreads();

    if (tid < 256) {
        int bb = tid >> 6, i = (tid >> 3) & 7, j = tid & 7;
        if (i != j) {
            float d2 = 0.f;
#pragma unroll
            for (int f = 0; f < NF; f++) {
                float d = smu[bb][i][f] - smu[bb][j][f];
                d2 = fmaf(d, d, d2);
            }
            float t = 3.0f - sqrtf(d2);           // 2 * DELTA_D
            t = fminf(fmaxf(t, 0.f), 100000.f);
            atomicAdd(&s_ldist[bb], t * t);
        } else {
            float d2 = 0.f;
#pragma unroll
            for (int f = 0; f < NF; f++)
                d2 = fmaf(smu[bb][i][f], smu[bb][i][f], d2);
            atomicAdd(&s_lreg[bb], sqrtf(d2));
            atomicAdd(&s_inv[bb], 1.0f / cnt_cache);
        }
    }
    __syncthreads();

    if (tid == 0) {
        float total = 0.f;
#pragma unroll
        for (int q = 0; q < BN; q++) {
            float dq = __ldcg(&g_s.dist[q]);
            float l_var  = dq * s_inv[q] / (float)CC;
            float l_dist = s_ldist[q] / (float)(CC * (CC - 1));
            float l_reg  = s_lreg[q] / (float)CC;
            total += l_var + l_dist + 0.001f * l_reg;
        }
        out[0] = total / (float)BN;
    }
    __syncthreads();

    // ---- scratch self-reset for the next graph replay ----
    {
        float* sc = (float*)&g_s;
        if (tid < 292) sc[tid] = 0.f;   // sums(256) + counts(32) + dist(4)
        if (tid == 0) { g_s.arrive = 0u; g_s.release = 0u; g_s.ticket = 0u; }
    }
}

extern "C" void kernel_launch(void* const* d_in, const int* in_sizes, int n_in,
                              void* d_out, int out_size) {
    const float* pred = (const float*)d_in[0];
    const int*   tgt  = (const int*)d_in[1];
    float*       out  = (float*)d_out;
    (void)in_sizes; (void)n_in; (void)out_size;

    static bool attr_done = false;
    if (!attr_done) {
        cudaFuncSetAttribute(k_all, cudaFuncAttributeMaxDynamicSharedMemorySize,
                             SMEM_TOTAL);
        attr_done = true;
    }

    k_all<<<NBLK, NTHR, SMEM_TOTAL>>>(pred, tgt, out);
}

// round 15
// speedup vs baseline: 1.0767x; 1.0767x over previous
#include <cuda_runtime.h>

#define BN   4
#define NF   8
#define CC   8
#define NPIX (512 * 512)
#define NG   (NPIX / 4)
#define P2_TOTAL (256 * BN)

struct Scratch {
    float sums[BN][CC][NF];   // 256
    float counts[BN][CC];     // 32
    float dist[BN];           // 4
    unsigned int ticket;
};
__device__ Scratch g_s;   // zero-init at module load; self-reset every run

__device__ __forceinline__ unsigned long long ffma2(unsigned long long a,
                                                    unsigned long long b,
                                                    unsigned long long c) {
    unsigned long long d;
    asm("fma.rn.f32x2 %0, %1, %2, %3;" : "=l"(d) : "l"(a), "l"(b), "l"(c));
    return d;
}
__device__ __forceinline__ unsigned long long fadd2(unsigned long long a,
                                                    unsigned long long b) {
    unsigned long long d;
    asm("add.rn.f32x2 %0, %1, %2;" : "=l"(d) : "l"(a), "l"(b));
    return d;
}
__device__ __forceinline__ unsigned long long pack2(float lo, float hi) {
    unsigned long long r;
    asm("mov.b64 %0, {%1, %2};" : "=l"(r) : "f"(lo), "f"(hi));
    return r;
}
__device__ __forceinline__ void unpack2(unsigned long long v, float& lo, float& hi) {
    asm("mov.b64 {%0, %1}, %2;" : "=f"(lo), "=f"(hi) : "l"(v));
}
__device__ __forceinline__ float f4get(const float4 v, int i) {
    return i == 0 ? v.x : i == 1 ? v.y : i == 2 ? v.z : v.w;
}
__device__ __forceinline__ int i4get(const int4 v, int i) {
    return i == 0 ? v.x : i == 1 ? v.y : i == 2 ? v.z : v.w;
}

// ---------------------------------------------------------------------------
// Pass 1 (exact R2): per-cluster counts + feature sums. float4 loads, packed
// f32x2 FMA one-hot accumulate, int counts on ALU pipe.
// ---------------------------------------------------------------------------
__global__ void __launch_bounds__(128) k_pass1(const float* __restrict__ pred,
                                               const int* __restrict__ tgt) {
    const int b = blockIdx.y;
    const float4* p = (const float4*)(pred + (size_t)b * NF * NPIX);
    const int4*   g = (const int4*)(tgt + (size_t)b * NPIX);
    const unsigned long long ONE2 = 0x3F8000003F800000ull;

    unsigned long long acc[CC][4];
    int icnt[CC];
#pragma unroll
    for (int c = 0; c < CC; c++) {
        icnt[c] = 0;
#pragma unroll
        for (int k = 0; k < 4; k++) acc[c][k] = 0ull;
    }

    for (int n = blockIdx.x * blockDim.x + threadIdx.x; n < NG;
         n += gridDim.x * blockDim.x) {
        int4 lab4 = g[n];
        float4 v[NF];
#pragma unroll
        for (int f = 0; f < NF; f++) v[f] = p[f * (NPIX / 4) + n];

#pragma unroll
        for (int px = 0; px < 4; px++) {
            int lab = i4get(lab4, px);
            unsigned long long pr[4];
#pragma unroll
            for (int k = 0; k < 4; k++)
                pr[k] = pack2(f4get(v[2 * k], px), f4get(v[2 * k + 1], px));
#pragma unroll
            for (int c = 0; c < CC; c++) {
                bool hit = (lab == c);
                unsigned long long m2 = hit ? ONE2 : 0ull;
                icnt[c] += hit;
#pragma unroll
                for (int k = 0; k < 4; k++) acc[c][k] = ffma2(m2, pr[k], acc[c][k]);
            }
        }
    }

    // warp tree-reduce (packed adds)
#pragma unroll
    for (int c = 0; c < CC; c++) {
#pragma unroll
        for (int k = 0; k < 4; k++) {
            unsigned long long x = acc[c][k];
#pragma unroll
            for (int o = 16; o > 0; o >>= 1)
                x = fadd2(x, __shfl_down_sync(0xffffffffu, x, o));
            acc[c][k] = x;
        }
        int ic = icnt[c];
#pragma unroll
        for (int o = 16; o > 0; o >>= 1) ic += __shfl_down_sync(0xffffffffu, ic, o);
        icnt[c] = ic;
    }

    __shared__ float sw[4][72];  // 4 warps x (64 sums + 8 counts)
    int tid = threadIdx.x, wid = tid >> 5, lane = tid & 31;
    if (lane == 0) {
#pragma unroll
        for (int c = 0; c < CC; c++) {
#pragma unroll
            for (int k = 0; k < 4; k++) {
                float lo, hi;
                unpack2(acc[c][k], lo, hi);
                sw[wid][c * NF + 2 * k]     = lo;
                sw[wid][c * NF + 2 * k + 1] = hi;
            }
            sw[wid][64 + c] = (float)icnt[c];
        }
    }
    __syncthreads();
    if (tid < 72) {
        float s = sw[0][tid] + sw[1][tid] + sw[2][tid] + sw[3][tid];
        if (tid < 64)
            atomicAdd(&((float*)g_s.sums)[b * 64 + tid], s);
        else
            atomicAdd(&g_s.counts[b][tid - 64], s);
    }
}

// ---------------------------------------------------------------------------
// Pass 2 (exact R2) + finalize (last-block ticket) + scratch self-reset.
// ---------------------------------------------------------------------------
__global__ void __launch_bounds__(256) k_pass2(const float* __restrict__ pred,
                                               const int* __restrict__ tgt,
                                               float* __restrict__ out) {
    const int b = blockIdx.y;
    __shared__ float smean[NF][CC];
    int tid = threadIdx.x;
    if (tid < 64) {
        int c = tid & 7, f = tid >> 3;
        smean[f][c] = g_s.sums[b][c][f] / g_s.counts[b][c];
    }
    __syncthreads();

    const float4* p = (const float4*)(pred + (size_t)b * NF * NPIX);
    const int4*   g = (const int4*)(tgt + (size_t)b * NPIX);
    float local = 0.f;
    for (int n = blockIdx.x * blockDim.x + threadIdx.x; n < NG;
         n += gridDim.x * blockDim.x) {
        int4 lab4 = g[n];
        float4 v[NF];
#pragma unroll
        for (int f = 0; f < NF; f++) v[f] = p[f * (NPIX / 4) + n];
#pragma unroll
        for (int px = 0; px < 4; px++) {
            int lab = i4get(lab4, px);
            float d2 = 0.f;
#pragma unroll
            for (int f = 0; f < NF; f++) {
                float d = smean[f][lab] - f4get(v[f], px);
                d2 = fmaf(d, d, d2);
            }
            float t = sqrtf(d2) - 0.5f;           // DELTA_V
            t = fminf(fmaxf(t, 0.f), 100000.f);
            local = fmaf(t, t, local);
        }
    }

#pragma unroll
    for (int o = 16; o > 0; o >>= 1)
        local += __shfl_down_sync(0xffffffffu, local, o);
    __shared__ float sred[8];
    if ((tid & 31) == 0) sred[tid >> 5] = local;
    __syncthreads();
    if (tid == 0) {
        float s = 0.f;
#pragma unroll
        for (int w = 0; w < 8; w++) s += sred[w];
        atomicAdd(&g_s.dist[b], s);
    }

    // ---- last-block finalize ----
    __shared__ bool s_last;
    __threadfence();
    if (tid == 0) {
        unsigned int t = atomicAdd(&g_s.ticket, 1u);
        s_last = (t == P2_TOTAL - 1);
    }
    __syncthreads();
    if (!s_last) return;

    __shared__ float smu[BN][CC][NF];
    __shared__ float s_ldist[BN], s_lreg[BN], s_inv[BN];
    float cnt_cache = 1.f;
    {
        int bb = tid >> 6, i = (tid >> 3) & 7, j = tid & 7;
        cnt_cache = __ldcg(&g_s.counts[bb][i]);
        smu[bb][i][j] = __ldcg(&g_s.sums[bb][i][j]) / cnt_cache;
    }
    if (tid < BN) { s_ldist[tid] = 0.f; s_lreg[tid] = 0.f; s_inv[tid] = 0.f; }
    __syncthreads();

    {
        int bb = tid >> 6, i = (tid >> 3) & 7, j = tid & 7;
        if (i != j) {
            float d2 = 0.f;
#pragma unroll
            for (int f = 0; f < NF; f++) {
                float d = smu[bb][i][f] - smu[bb][j][f];
                d2 = fmaf(d, d, d2);
            }
            float t = 3.0f - sqrtf(d2);           // 2 * DELTA_D
            t = fminf(fmaxf(t, 0.f), 100000.f);
            atomicAdd(&s_ldist[bb], t * t);
        } else {
            float d2 = 0.f;
#pragma unroll
            for (int f = 0; f < NF; f++)
                d2 = fmaf(smu[bb][i][f], smu[bb][i][f], d2);
            atomicAdd(&s_lreg[bb], sqrtf(d2));
            atomicAdd(&s_inv[bb], 1.0f / cnt_cache);
        }
    }
    __syncthreads();

    if (tid == 0) {
        float total = 0.f;
#pragma unroll
        for (int q = 0; q < BN; q++) {
            float dq = __ldcg(&g_s.dist[q]);
            float l_var  = dq * s_inv[q] / (float)CC;
            float l_dist = s_ldist[q] / (float)(CC * (CC - 1));
            float l_reg  = s_lreg[q] / (float)CC;
            total += l_var + l_dist + 0.001f * l_reg;
        }
        out[0] = total / (float)BN;
    }
    __syncthreads();

    // ---- scratch self-reset for the next graph replay (race-free: this is
    // the last-ticket block; all atomics to g_s have completed) ----
    {
        float* sc = (float*)&g_s;
        sc[tid] = 0.f;                 // sums[0..255]
        if (tid < 36) sc[256 + tid] = 0.f;  // counts(32) + dist(4)
        if (tid == 0) g_s.ticket = 0u;
    }
}

extern "C" void kernel_launch(void* const* d_in, const int* in_sizes, int n_in,
                              void* d_out, int out_size) {
    const float* pred = (const float*)d_in[0];
    const int*   tgt  = (const int*)d_in[1];
    float*       out  = (float*)d_out;
    (void)in_sizes; (void)n_in; (void)out_size;

    dim3 grid(256, BN);
    k_pass1<<<grid, 128>>>(pred, tgt);
    k_pass2<<<grid, 256>>>(pred, tgt, out);
}